// round 12
// baseline (speedup 1.0000x reference)
#include <cuda_runtime.h>
#include <cuda_bf16.h>

#define NN 100000
#define HH 256

// Per-node scratch (device globals: no allocation allowed in kernel_launch)
__device__ float4   g_zl[NN];        // {z0, z1, el, pad} per node (src-side gather)
__device__ float    g_er[NN];        // z . attn_r (dest term) — separate read-only
                                     // array (R5: co-locating with atomic target
                                     // caused sector-RMW contention)
__device__ float4   g_acc[NN];       // {denom, num0, num1, pad}

// K1: 8-lanes-per-node GEMM [N,256]@[256,2] -> zl, er; init accumulators.
// (R9 shape — measured 20.0us: full 128B line per 8-lane group, 8 float4/lane.)
__global__ void k_gemm(const float* __restrict__ input,
                       const float* __restrict__ W,
                       const float* __restrict__ attn_l,
                       const float* __restrict__ attn_r) {
    __shared__ float sw0[HH], sw1[HH];
    int t = threadIdx.x;
    { sw0[t] = W[t * 2 + 0]; sw1[t] = W[t * 2 + 1]; }   // t covers 0..255 == HH
    __syncthreads();

    int grp = t >> 3, gl = t & 7;
    int node = blockIdx.x * 32 + grp;
    if (node >= NN) return;

    const float4* row4 = (const float4*)(input + (size_t)node * HH);
    float d0 = 0.f, d1 = 0.f;
#pragma unroll
    for (int j = 0; j < 8; j++) {
        int k = j * 8 + gl;                  // lanes 0..7 -> contiguous 128B line
        float4 v = row4[k];
        int b = 4 * k;
        d0 = fmaf(v.x, sw0[b+0], d0); d1 = fmaf(v.x, sw1[b+0], d1);
        d0 = fmaf(v.y, sw0[b+1], d0); d1 = fmaf(v.y, sw1[b+1], d1);
        d0 = fmaf(v.z, sw0[b+2], d0); d1 = fmaf(v.z, sw1[b+2], d1);
        d0 = fmaf(v.w, sw0[b+3], d0); d1 = fmaf(v.w, sw1[b+3], d1);
    }
#pragma unroll
    for (int o = 4; o; o >>= 1) {
        d0 += __shfl_xor_sync(0xFFFFFFFFu, d0, o);
        d1 += __shfl_xor_sync(0xFFFFFFFFu, d1, o);
    }
    if (gl == 0) {
        float el = d0 * attn_l[0] + d1 * attn_l[1];
        float er = d0 * attn_r[0] + d1 * attn_r[1];
        g_zl[node]  = make_float4(d0, d1, el, 0.f);
        g_er[node]  = er;
        g_acc[node] = make_float4(0.f, 0.f, 0.f, 0.f);
    }
}

// K2: per-edge softmax accumulation WITHOUT max-subtraction (shift-invariant;
// e is bounded far inside fp32 exp range for this distribution).
// 16 edges/thread in two software-pipelined half-batches: all 32 gathers are
// issued before the first atomic, and batch-A atomics overlap batch-B load
// latency. Edge streams evict-first so they don't flush warm L2.
__global__ void k_esum_g(const int4* __restrict__ src4, const int4* __restrict__ dst4,
                         int E4) {
    int i = blockIdx.x * blockDim.x + threadIdx.x;
    int base = i * 4;                        // 4 int4 = 16 edges
    if (base >= E4) return;

    int4 s0 = __ldcs(&src4[base]);
    int4 d0 = __ldcs(&dst4[base]);
    int4 s1 = __ldcs(&src4[base + 1]);
    int4 d1 = __ldcs(&dst4[base + 1]);
    int4 s2 = __ldcs(&src4[base + 2]);
    int4 d2 = __ldcs(&dst4[base + 2]);
    int4 s3 = __ldcs(&src4[base + 3]);
    int4 d3 = __ldcs(&dst4[base + 3]);

    int ssA[8] = {s0.x, s0.y, s0.z, s0.w, s1.x, s1.y, s1.z, s1.w};
    int ddA[8] = {d0.x, d0.y, d0.z, d0.w, d1.x, d1.y, d1.z, d1.w};
    int ssB[8] = {s2.x, s2.y, s2.z, s2.w, s3.x, s3.y, s3.z, s3.w};
    int ddB[8] = {d2.x, d2.y, d2.z, d2.w, d3.x, d3.y, d3.z, d3.w};

    // Issue ALL gathers (32 outstanding loads) before any consumption
    float4 zA[8], zB[8];
    float  eA[8], eB[8];
#pragma unroll
    for (int j = 0; j < 8; j++) { zA[j] = __ldg(&g_zl[ssA[j]]); eA[j] = __ldg(&g_er[ddA[j]]); }
#pragma unroll
    for (int j = 0; j < 8; j++) { zB[j] = __ldg(&g_zl[ssB[j]]); eB[j] = __ldg(&g_er[ddB[j]]); }

    // Process batch A (its atomics overlap batch B's in-flight loads)
#pragma unroll
    for (int j = 0; j < 8; j++) {
        float e = zA[j].z + eA[j];
        e = (e > 0.f) ? e : 0.2f * e;        // leaky_relu(0.2)
        float ex = __expf(e);
        atomicAdd(&g_acc[ddA[j]], make_float4(ex, ex * zA[j].x, ex * zA[j].y, 0.f));
    }
    // Process batch B
#pragma unroll
    for (int j = 0; j < 8; j++) {
        float e = zB[j].z + eB[j];
        e = (e > 0.f) ? e : 0.2f * e;
        float ex = __expf(e);
        atomicAdd(&g_acc[ddB[j]], make_float4(ex, ex * zB[j].x, ex * zB[j].y, 0.f));
    }
}

// K3 (fused epilogue + gate + scale):
// Each block owns 512 contiguous float4s = 8 rows. Threads 0-7 compute the 8
// gate scalars ONCE into smem, then all threads apply them. Block order
// REVERSED so first-scheduled blocks read the rows k_gemm cached most recently.
#define TOT4 (NN * (HH / 4))                 // 6,400,000 float4s = 12500 * 512
__global__ void k_out(const float4* __restrict__ input, float4* __restrict__ out,
                      const float* __restrict__ x, const float* __restrict__ bias) {
    __shared__ float ssc[8];
    int b = (int)gridDim.x - 1 - (int)blockIdx.x;      // reverse traversal
    int base = b * 512;                      // first float4 of this block
    int t = threadIdx.x;

    if (t < 8) {
        int row = (base >> 6) + t;           // 64 float4 per row
        float4 a = __ldg(&g_acc[row]);
        float  xv = __ldg(&x[row]);
        float b0 = __ldg(&bias[0]);
        float b1 = __ldg(&bias[1]);
        float inv = 1.f / a.x;
        float c0 = a.y * inv + b0;
        float c1 = a.z * inv + b1;
        float arg = fmaf(xv, fmaxf(c0, 0.f), fmaxf(c1, 0.f));
        ssc[t] = 1.f / (1.f + __expf(-arg));
    }
    __syncthreads();

    int i1 = base + t;                       // rows 0..3 of the block
    int i2 = base + t + 256;                 // rows 4..7 of the block
    float4 v1 = __ldcs(&input[i1]);
    float4 v2 = __ldcs(&input[i2]);
    float s1 = ssc[t >> 6];
    float s2 = ssc[4 + (t >> 6)];
    v1.x *= s1; v1.y *= s1; v1.z *= s1; v1.w *= s1;
    v2.x *= s2; v2.y *= s2; v2.z *= s2; v2.w *= s2;
    __stcs(&out[i1], v1);
    __stcs(&out[i2], v2);
}

extern "C" void kernel_launch(void* const* d_in, const int* in_sizes, int n_in,
                              void* d_out, int out_size) {
    const float* input  = (const float*)d_in[0];
    const float* x      = (const float*)d_in[1];
    // d_in[2] = degree (unused)
    const int*   esrc   = (const int*)d_in[3];
    const int*   edst   = (const int*)d_in[4];
    const float* W      = (const float*)d_in[5];
    const float* attn_l = (const float*)d_in[6];
    const float* attn_r = (const float*)d_in[7];
    const float* bias   = (const float*)d_in[8];
    float* out = (float*)d_out;

    int E  = in_sizes[3];
    int E4 = E / 4;            // 800,000 int4s per edge array
    int nE = (E4 + 3) / 4;     // threads processing 4 int4 (16 edges) each

    k_gemm<<<(NN + 31) / 32, 256>>>(input, W, attn_l, attn_r);
    k_esum_g<<<(nE + 255) / 256, 256>>>((const int4*)esrc, (const int4*)edst, E4);
    k_out<<<TOT4 / 512, 256>>>((const float4*)input, (float4*)out, x, bias);
}

// round 13
// speedup vs baseline: 1.0811x; 1.0811x over previous
#include <cuda_runtime.h>
#include <cuda_bf16.h>

#define NN 100000
#define HH 256

// Per-node scratch (device globals: no allocation allowed in kernel_launch)
__device__ float4   g_zl[NN];        // {z0, z1, el, pad} per node (src-side gather)
__device__ float    g_er[NN];        // z . attn_r (dest term) — separate read-only
                                     // array (R5: co-locating with the atomic
                                     // target caused sector-RMW contention)
__device__ float4   g_acc[NN];       // {denom, num0, num1, pad}

// K1: 8-lanes-per-node GEMM [N,256]@[256,2] -> zl, er; init accumulators.
// (Proven shape: full 128B line per 8-lane group, 8 float4/lane, ~20.7us.)
__global__ void k_gemm(const float* __restrict__ input,
                       const float* __restrict__ W,
                       const float* __restrict__ attn_l,
                       const float* __restrict__ attn_r) {
    __shared__ float sw0[HH], sw1[HH];
    int t = threadIdx.x;
    { sw0[t] = W[t * 2 + 0]; sw1[t] = W[t * 2 + 1]; }   // t covers 0..255 == HH
    __syncthreads();

    int grp = t >> 3, gl = t & 7;
    int node = blockIdx.x * 32 + grp;
    if (node >= NN) return;

    const float4* row4 = (const float4*)(input + (size_t)node * HH);
    float d0 = 0.f, d1 = 0.f;
#pragma unroll
    for (int j = 0; j < 8; j++) {
        int k = j * 8 + gl;                  // lanes 0..7 -> contiguous 128B line
        float4 v = row4[k];
        int b = 4 * k;
        d0 = fmaf(v.x, sw0[b+0], d0); d1 = fmaf(v.x, sw1[b+0], d1);
        d0 = fmaf(v.y, sw0[b+1], d0); d1 = fmaf(v.y, sw1[b+1], d1);
        d0 = fmaf(v.z, sw0[b+2], d0); d1 = fmaf(v.z, sw1[b+2], d1);
        d0 = fmaf(v.w, sw0[b+3], d0); d1 = fmaf(v.w, sw1[b+3], d1);
    }
#pragma unroll
    for (int o = 4; o; o >>= 1) {
        d0 += __shfl_xor_sync(0xFFFFFFFFu, d0, o);
        d1 += __shfl_xor_sync(0xFFFFFFFFu, d1, o);
    }
    if (gl == 0) {
        float el = d0 * attn_l[0] + d1 * attn_l[1];
        float er = d0 * attn_r[0] + d1 * attn_r[1];
        g_zl[node]  = make_float4(d0, d1, el, 0.f);
        g_er[node]  = er;
        g_acc[node] = make_float4(0.f, 0.f, 0.f, 0.f);
    }
}

// K2: per-edge softmax accumulation WITHOUT max-subtraction (shift-invariant;
// e is bounded far inside fp32 exp range for this distribution).
// 8 edges/thread (proven shape). PDL: edge-index loads are independent of
// k_gemm, so they issue BEFORE cudaGridDependencySynchronize(), overlapping
// the gemm drain. Gathers/atomics (which DO depend on gemm) come after.
__global__ void k_esum_g(const int4* __restrict__ src4, const int4* __restrict__ dst4,
                         int E4) {
    int i = blockIdx.x * blockDim.x + threadIdx.x;
    int base = i * 2;

    int4 s0, d0, s1, d1;
    bool act = (base < E4);
    if (act) {
        s0 = __ldcs(&src4[base]);
        d0 = __ldcs(&dst4[base]);
        s1 = __ldcs(&src4[base + 1]);
        d1 = __ldcs(&dst4[base + 1]);
    }

    cudaGridDependencySynchronize();         // wait for k_gemm results
    if (!act) return;

    int ss[8] = {s0.x, s0.y, s0.z, s0.w, s1.x, s1.y, s1.z, s1.w};
    int dd[8] = {d0.x, d0.y, d0.z, d0.w, d1.x, d1.y, d1.z, d1.w};

    float4 z[8];
    float  erd[8];
#pragma unroll
    for (int j = 0; j < 8; j++) {
        z[j]   = __ldg(&g_zl[ss[j]]);        // {z0, z1, el, -}
        erd[j] = __ldg(&g_er[dd[j]]);
    }
#pragma unroll
    for (int j = 0; j < 8; j++) {
        float e = z[j].z + erd[j];
        e = (e > 0.f) ? e : 0.2f * e;        // leaky_relu(0.2)
        float ex = __expf(e);
        atomicAdd(&g_acc[dd[j]], make_float4(ex, ex * z[j].x, ex * z[j].y, 0.f));
    }
}

// K3 (fused epilogue + gate + scale): each block owns 512 contiguous float4s
// = 8 rows; threads 0-7 compute the 8 gate scalars into smem. Block order
// REVERSED to race k_gemm's L2 eviction front. PDL: the big input reads are
// independent of g_acc -> issued BEFORE cudaGridDependencySynchronize(),
// overlapping k_esum's tail on otherwise-idle DRAM.
#define TOT4 (NN * (HH / 4))                 // 6,400,000 float4s = 12500 * 512
__global__ void k_out(const float4* __restrict__ input, float4* __restrict__ out,
                      const float* __restrict__ x, const float* __restrict__ bias) {
    __shared__ float ssc[8];
    int b = (int)gridDim.x - 1 - (int)blockIdx.x;      // reverse traversal
    int base = b * 512;                      // first float4 of this block
    int t = threadIdx.x;

    int i1 = base + t;
    int i2 = base + t + 256;
    float4 v1 = __ldcs(&input[i1]);          // independent prefetch (pre-sync)
    float4 v2 = __ldcs(&input[i2]);
    float xv = 0.f, b0 = 0.f, b1 = 0.f;
    int row = (base >> 6) + t;               // only meaningful for t < 8
    if (t < 8) {
        xv = __ldg(&x[row]);                 // x/bias are const inputs: pre-sync OK
        b0 = __ldg(&bias[0]);
        b1 = __ldg(&bias[1]);
    }

    cudaGridDependencySynchronize();         // wait for k_esum's g_acc

    if (t < 8) {
        float4 a = __ldg(&g_acc[row]);
        float inv = 1.f / a.x;
        float c0 = a.y * inv + b0;
        float c1 = a.z * inv + b1;
        float arg = fmaf(xv, fmaxf(c0, 0.f), fmaxf(c1, 0.f));
        ssc[t] = 1.f / (1.f + __expf(-arg));
    }
    __syncthreads();

    float s1 = ssc[t >> 6];
    float s2 = ssc[4 + (t >> 6)];
    v1.x *= s1; v1.y *= s1; v1.z *= s1; v1.w *= s1;
    v2.x *= s2; v2.y *= s2; v2.z *= s2; v2.w *= s2;
    __stcs(&out[i1], v1);
    __stcs(&out[i2], v2);
}

template <typename... Args>
static inline void launch_pdl(void (*kern)(Args...), dim3 grid, dim3 block,
                              Args... args) {
    cudaLaunchConfig_t cfg = {};
    cfg.gridDim = grid;
    cfg.blockDim = block;
    cfg.dynamicSmemBytes = 0;
    cfg.stream = 0;                          // legacy default stream (captured)
    cudaLaunchAttribute at[1];
    at[0].id = cudaLaunchAttributeProgrammaticStreamSerialization;
    at[0].val.programmaticStreamSerializationAllowed = 1;
    cfg.attrs = at;
    cfg.numAttrs = 1;
    cudaLaunchKernelEx(&cfg, kern, args...);
}

extern "C" void kernel_launch(void* const* d_in, const int* in_sizes, int n_in,
                              void* d_out, int out_size) {
    const float* input  = (const float*)d_in[0];
    const float* x      = (const float*)d_in[1];
    // d_in[2] = degree (unused)
    const int*   esrc   = (const int*)d_in[3];
    const int*   edst   = (const int*)d_in[4];
    const float* W      = (const float*)d_in[5];
    const float* attn_l = (const float*)d_in[6];
    const float* attn_r = (const float*)d_in[7];
    const float* bias   = (const float*)d_in[8];
    float* out = (float*)d_out;

    int E  = in_sizes[3];
    int E4 = E / 4;            // 800,000 int4s per edge array
    int nE = (E4 + 1) / 2;     // threads processing 2 int4 (8 edges) each

    k_gemm<<<(NN + 31) / 32, 256>>>(input, W, attn_l, attn_r);
    launch_pdl(k_esum_g, dim3((nE + 255) / 256), dim3(256),
               (const int4*)esrc, (const int4*)edst, E4);
    launch_pdl(k_out, dim3(TOT4 / 512), dim3(256),
               (const float4*)input, (float4*)out, x, bias);
}